// round 15
// baseline (speedup 1.0000x reference)
#include <cuda_runtime.h>
#include <math.h>

#define NF   512
#define TK   196
#define EM   2560
#define HID  512
#define E4   (EM/4)
#define POOL_T 320
#define NTOP 64
#define KS_H 9
#define KS_F 16
#define TAILB 128

// ---------------- scratch (static device globals) ----------------------------
__device__ float g_pooled[NF * EM];         // layer-normed pooled features
__device__ float g_invn[NF];                // 1/||pooled_ln|| per frame
__device__ float g_tproj[HID];              // txt_ln @ W1_top + b1
__device__ float g_hp[KS_H * NF * HID];     // split-K partials of pooled_ln @ W1_bot
__device__ float g_fp[KS_F * NTOP * NF];    // split-K partials of top-64 f2f rows
__device__ float g_gates[NF];
__device__ int   g_order[NF];
__device__ unsigned int g_mask[NTOP * 16];  // f2f>0.98 bitmask for top-64 rows
__device__ unsigned int g_gctr = 0;         // grid-barrier counter (self-resetting)

// ---------------- software grid barrier (all blocks resident) -----------------
__device__ __forceinline__ void gbar(unsigned int goal) {
    __syncthreads();
    if (threadIdx.x == 0) {
        __threadfence();
        atomicAdd(&g_gctr, 1u);
        while (atomicAdd(&g_gctr, 0u) < goal) { __nanosleep(64); }
        __threadfence();
    }
    __syncthreads();
}

// ---------------- block reduce of two scalars --------------------------------
__device__ __forceinline__ void blk_reduce2(float& a, float& b, float* sm, int nwarp) {
    int lane = threadIdx.x & 31, wid = threadIdx.x >> 5;
#pragma unroll
    for (int o = 16; o > 0; o >>= 1) {
        a += __shfl_down_sync(0xffffffffu, a, o);
        b += __shfl_down_sync(0xffffffffu, b, o);
    }
    if (lane == 0) { sm[wid] = a; sm[wid + 16] = b; }
    __syncthreads();
    if (wid == 0) {
        a = lane < nwarp ? sm[lane] : 0.f;
        b = lane < nwarp ? sm[lane + 16] : 0.f;
#pragma unroll
        for (int o = 16; o > 0; o >>= 1) {
            a += __shfl_down_sync(0xffffffffu, a, o);
            b += __shfl_down_sync(0xffffffffu, b, o);
        }
        if (lane == 0) { sm[32] = a; sm[33] = b; }
    }
    __syncthreads();
    a = sm[32];
    b = sm[33];
    __syncthreads();
}

// ---------------- 1) pool+LN (blocks 0..511) / txt-LN+proj (blocks 512..527) --
__global__ __launch_bounds__(POOL_T) void pool_tproj_k(
    const float* __restrict__ img, const float* __restrict__ g,
    const float* __restrict__ b,
    const float* __restrict__ xt, const float* __restrict__ gt,
    const float* __restrict__ bt, const float* __restrict__ W1,
    const float* __restrict__ b1) {
    const int tid = threadIdx.x;

    if (blockIdx.x < NF) {
        const int f = blockIdx.x;
        const float4* base = reinterpret_cast<const float4*>(img) + (size_t)f * TK * E4;
        const int c0 = tid, c1 = tid + POOL_T;

        float4 a0 = make_float4(0.f, 0.f, 0.f, 0.f);
        float4 a1 = make_float4(0.f, 0.f, 0.f, 0.f);
        for (int t = 0; t < TK; t += 4) {           // 196 = 49*4, MLP=8
            float4 v[8];
#pragma unroll
            for (int u = 0; u < 4; ++u) {
                v[2 * u]     = __ldcs(base + (size_t)(t + u) * E4 + c0);
                v[2 * u + 1] = __ldcs(base + (size_t)(t + u) * E4 + c1);
            }
#pragma unroll
            for (int u = 0; u < 4; ++u) {
                a0.x += v[2*u].x;   a0.y += v[2*u].y;   a0.z += v[2*u].z;   a0.w += v[2*u].w;
                a1.x += v[2*u+1].x; a1.y += v[2*u+1].y; a1.z += v[2*u+1].z; a1.w += v[2*u+1].w;
            }
        }
        const float inv = 1.0f / (float)TK;
        a0.x *= inv; a0.y *= inv; a0.z *= inv; a0.w *= inv;
        a1.x *= inv; a1.y *= inv; a1.z *= inv; a1.w *= inv;

        float s = a0.x + a0.y + a0.z + a0.w + a1.x + a1.y + a1.z + a1.w;
        float q = a0.x*a0.x + a0.y*a0.y + a0.z*a0.z + a0.w*a0.w
                + a1.x*a1.x + a1.y*a1.y + a1.z*a1.z + a1.w*a1.w;

        __shared__ float sm[34];
        blk_reduce2(s, q, sm, POOL_T / 32);
        const float mean = s / (float)EM;
        const float var  = q / (float)EM - mean * mean;
        const float rstd = rsqrtf(var + 1e-5f);

        const float4 g0 = __ldg(reinterpret_cast<const float4*>(g) + c0);
        const float4 g1 = __ldg(reinterpret_cast<const float4*>(g) + c1);
        const float4 b0 = __ldg(reinterpret_cast<const float4*>(b) + c0);
        const float4 b1v = __ldg(reinterpret_cast<const float4*>(b) + c1);

        float4 y0, y1;
        y0.x = (a0.x - mean) * rstd * g0.x + b0.x;
        y0.y = (a0.y - mean) * rstd * g0.y + b0.y;
        y0.z = (a0.z - mean) * rstd * g0.z + b0.z;
        y0.w = (a0.w - mean) * rstd * g0.w + b0.w;
        y1.x = (a1.x - mean) * rstd * g1.x + b1v.x;
        y1.y = (a1.y - mean) * rstd * g1.y + b1v.y;
        y1.z = (a1.z - mean) * rstd * g1.z + b1v.z;
        y1.w = (a1.w - mean) * rstd * g1.w + b1v.w;

        float4* pooled4 = reinterpret_cast<float4*>(g_pooled) + (size_t)f * E4;
        pooled4[c0] = y0;
        pooled4[c1] = y1;

        float q2 = y0.x*y0.x + y0.y*y0.y + y0.z*y0.z + y0.w*y0.w
                 + y1.x*y1.x + y1.y*y1.y + y1.z*y1.z + y1.w*y1.w;
        float dummy = 0.f;
        blk_reduce2(q2, dummy, sm, POOL_T / 32);
        if (tid == 0) g_invn[f] = 1.0f / fmaxf(sqrtf(q2), 1e-8f);
    } else {
        __shared__ float st[EM];
        __shared__ float smt[34];
        __shared__ float red[10][33];
        const int blk = blockIdx.x - NF;            // 0..15
        float xs[8];
        float s = 0.f, q = 0.f;
#pragma unroll
        for (int k = 0; k < 8; ++k) {               // 320*8 = 2560
            int e = tid + k * POOL_T;
            xs[k] = __ldg(xt + e);
            s += xs[k];
            q += xs[k] * xs[k];
        }
        blk_reduce2(s, q, smt, POOL_T / 32);
        const float mean = s / (float)EM;
        const float var  = q / (float)EM - mean * mean;
        const float rstd = rsqrtf(var + 1e-5f);
#pragma unroll
        for (int k = 0; k < 8; ++k) {
            int e = tid + k * POOL_T;
            st[e] = (xs[k] - mean) * rstd * __ldg(gt + e) + __ldg(bt + e);
        }
        __syncthreads();

        const int j = blk * 32 + (tid & 31);
        const int c = tid >> 5;                     // 10 warps, 256-elem K-chunks
        const float* wp = W1 + (size_t)(c * 256) * HID + j;
        float acc[4] = {0.f, 0.f, 0.f, 0.f};
        for (int e = 0; e < 256; e += 4) {
#pragma unroll
            for (int u = 0; u < 4; ++u)
                acc[u] += st[c * 256 + e + u] * __ldg(wp + (size_t)(e + u) * HID);
        }
        float v = (acc[0] + acc[1]) + (acc[2] + acc[3]);
        red[c][tid & 31] = v;
        __syncthreads();
        if (c == 0) {
            float r = 0.f;
#pragma unroll
            for (int si = 0; si < 10; ++si) r += red[si][tid & 31];
            g_tproj[j] = r + __ldg(b1 + j);
        }
    }
}

// ---------------- 2) h-GEMM: 128x128 tile, 8x8 microtile, split-K 9 -----------
__global__ __launch_bounds__(256) void gemm_h_k(const float* __restrict__ Wb) {
    const int z = blockIdx.z;
    const int kb = z * 288;
    const int klen = (z == 8) ? 256 : 288;
    const int NT = klen / 8;

    const int rb = blockIdx.y * 128, cb = blockIdx.x * 128;
    const int t = threadIdx.x;
    const int alr = t >> 1, alk = (t & 1) * 4;   // A: 128 rows x 2 k-quads
    const int bk = t >> 5, bc = (t & 31) * 4;    // B: 8 k x 32 col-quads
    const int ty = t >> 4, tx = t & 15;

    const float* Ap = g_pooled + (size_t)(rb + alr) * EM + kb + alk;
    const float* Bp = Wb + (size_t)(kb + bk) * HID + cb + bc;

    __shared__ __align__(16) float As[2][8][132];
    __shared__ __align__(16) float Bs[2][8][132];

    float4 pa = *reinterpret_cast<const float4*>(Ap);
    float4 pb = *reinterpret_cast<const float4*>(Bp);
    As[0][alk + 0][alr] = pa.x;
    As[0][alk + 1][alr] = pa.y;
    As[0][alk + 2][alr] = pa.z;
    As[0][alk + 3][alr] = pa.w;
    *reinterpret_cast<float4*>(&Bs[0][bk][bc]) = pb;
    __syncthreads();

    float acc[8][8];
#pragma unroll
    for (int i = 0; i < 8; ++i)
#pragma unroll
        for (int j = 0; j < 8; ++j) acc[i][j] = 0.f;

    for (int kt = 0; kt < NT; ++kt) {
        const int buf = kt & 1;
        if (kt + 1 < NT) {
            pa = *reinterpret_cast<const float4*>(Ap + (kt + 1) * 8);
            pb = *reinterpret_cast<const float4*>(Bp + (size_t)(kt + 1) * 8 * HID);
        }
#pragma unroll
        for (int kk = 0; kk < 8; ++kk) {
            float4 a0 = *reinterpret_cast<const float4*>(&As[buf][kk][ty * 8]);
            float4 a1 = *reinterpret_cast<const float4*>(&As[buf][kk][ty * 8 + 4]);
            float4 b0 = *reinterpret_cast<const float4*>(&Bs[buf][kk][tx * 8]);
            float4 b1 = *reinterpret_cast<const float4*>(&Bs[buf][kk][tx * 8 + 4]);
            float ar[8] = {a0.x, a0.y, a0.z, a0.w, a1.x, a1.y, a1.z, a1.w};
            float br[8] = {b0.x, b0.y, b0.z, b0.w, b1.x, b1.y, b1.z, b1.w};
#pragma unroll
            for (int i = 0; i < 8; ++i)
#pragma unroll
                for (int j = 0; j < 8; ++j) acc[i][j] += ar[i] * br[j];
        }
        if (kt + 1 < NT) {
            const int nb = buf ^ 1;
            As[nb][alk + 0][alr] = pa.x;
            As[nb][alk + 1][alr] = pa.y;
            As[nb][alk + 2][alr] = pa.z;
            As[nb][alk + 3][alr] = pa.w;
            *reinterpret_cast<float4*>(&Bs[nb][bk][bc]) = pb;
            __syncthreads();
        }
    }

    float* C = g_hp + (size_t)z * NF * HID;
#pragma unroll
    for (int i = 0; i < 8; ++i) {
        float* cp = C + (size_t)(rb + ty * 8 + i) * HID + cb + tx * 8;
        *reinterpret_cast<float4*>(cp) =
            make_float4(acc[i][0], acc[i][1], acc[i][2], acc[i][3]);
        *reinterpret_cast<float4*>(cp + 4) =
            make_float4(acc[i][4], acc[i][5], acc[i][6], acc[i][7]);
    }
}

// ---------------- 3) fused tail: gates -> sort -> f2f -> mask -> scan ---------
// 128 blocks x 256 threads, all co-resident (1 block/SM) -> spin barrier safe.
__global__ __launch_bounds__(256) void tail_k(
    const float* __restrict__ W2, const float* __restrict__ b2,
    float* __restrict__ out) {
    __shared__ __align__(16) unsigned char sraw[17408];
    __shared__ int s_count, s_done, s_cur, s_take;
    __shared__ float sred[8];
    __shared__ int sredi[8];
    const int tid = threadIdx.x;
    const int bid = blockIdx.x;

    // ---- P1: gates, 4 frames per block (64 threads per frame) ----------------
    {
        const int fr = bid * 4 + (tid >> 6);
        const int l  = tid & 63;
        float v = 0.f;
#pragma unroll
        for (int h = 0; h < 2; ++h) {
            const int c = l + h * 64;
            float4 hv = reinterpret_cast<const float4*>(g_tproj)[c];
#pragma unroll
            for (int s = 0; s < KS_H; ++s) {
                float4 p = reinterpret_cast<const float4*>(
                    g_hp + (size_t)s * NF * HID + (size_t)fr * HID)[c];
                hv.x += p.x; hv.y += p.y; hv.z += p.z; hv.w += p.w;
            }
            const float4 w = __ldg(reinterpret_cast<const float4*>(W2) + c);
            v += fmaxf(hv.x, 0.f) * w.x + fmaxf(hv.y, 0.f) * w.y
               + fmaxf(hv.z, 0.f) * w.z + fmaxf(hv.w, 0.f) * w.w;
        }
#pragma unroll
        for (int o = 16; o > 0; o >>= 1) v += __shfl_down_sync(0xffffffffu, v, o);
        if ((tid & 31) == 0) sred[tid >> 5] = v;
        __syncthreads();
        if (l == 0) {
            const int gq = tid >> 6;
            float z = sred[2 * gq] + sred[2 * gq + 1] + __ldg(b2);
            g_gates[fr] = 1.0f / (1.0f + expf(-z));
        }
    }
    gbar(TAILB * 1);

    // ---- P2: stable descending rank-sort, 4 keys per block -------------------
    {
        unsigned long long* keys = reinterpret_cast<unsigned long long*>(sraw);
        unsigned int ba = __float_as_uint(g_gates[tid]);
        unsigned int bb = __float_as_uint(g_gates[tid + 256]);
        keys[tid]       = ((unsigned long long)(0xFFFFFFFFu - ba) << 32) | (unsigned int)tid;
        keys[tid + 256] = ((unsigned long long)(0xFFFFFFFFu - bb) << 32) | (unsigned int)(tid + 256);
        __syncthreads();
        const int i = bid * 4 + (tid >> 6);
        const int l = tid & 63;
        const unsigned long long me = keys[i];
        int r = 0;
#pragma unroll
        for (int j = 0; j < 8; ++j) r += (keys[l * 8 + j] < me) ? 1 : 0;
#pragma unroll
        for (int o = 16; o > 0; o >>= 1) r += __shfl_down_sync(0xffffffffu, r, o);
        if ((tid & 31) == 0) sredi[tid >> 5] = r;
        __syncthreads();
        if (l == 0) {
            const int gq = tid >> 6;
            g_order[sredi[2 * gq] + sredi[2 * gq + 1]] = i;
        }
    }
    gbar(TAILB * 2);

    // ---- P3: f2f GEMM (top-64 rows), 64x64 tile, split-K 16 ------------------
    {
        constexpr int KCH = EM / KS_F;               // 160
        constexpr int NT  = KCH / 16;                // 10
        float (*As)[16][68] = reinterpret_cast<float(*)[16][68]>(sraw);
        float (*Bs)[16][68] = reinterpret_cast<float(*)[16][68]>(sraw + 2 * 16 * 68 * 4);

        const int cb = (bid & 7) * 64;
        const int z  = bid >> 3;                     // 0..15
        const int kb = z * KCH;
        float* C = g_fp + (size_t)z * NTOP * NF;

        const int t  = tid;
        const int lr = t >> 2, lk = (t & 3) * 4;
        const int ty = t >> 4, tx = t & 15;

        const int arow = g_order[lr];
        const float* Ap = g_pooled + (size_t)arow * EM + kb + lk;
        const float* Bp = g_pooled + (size_t)(cb + lr) * EM + kb + lk;

        float4 pa = *reinterpret_cast<const float4*>(Ap);
        float4 pb = *reinterpret_cast<const float4*>(Bp);
        As[0][lk + 0][lr] = pa.x;
        As[0][lk + 1][lr] = pa.y;
        As[0][lk + 2][lr] = pa.z;
        As[0][lk + 3][lr] = pa.w;
        Bs[0][lk + 0][lr] = pb.x;
        Bs[0][lk + 1][lr] = pb.y;
        Bs[0][lk + 2][lr] = pb.z;
        Bs[0][lk + 3][lr] = pb.w;
        __syncthreads();

        float acc[4][4];
#pragma unroll
        for (int i = 0; i < 4; ++i)
#pragma unroll
            for (int j = 0; j < 4; ++j) acc[i][j] = 0.f;

        for (int kt = 0; kt < NT; ++kt) {
            const int buf = kt & 1;
            if (kt + 1 < NT) {
                pa = *reinterpret_cast<const float4*>(Ap + (kt + 1) * 16);
                pb = *reinterpret_cast<const float4*>(Bp + (kt + 1) * 16);
            }
#pragma unroll
            for (int kk = 0; kk < 16; ++kk) {
                float4 av = *reinterpret_cast<const float4*>(&As[buf][kk][ty * 4]);
                float4 bv = *reinterpret_cast<const float4*>(&Bs[buf][kk][tx * 4]);
                float ar[4] = {av.x, av.y, av.z, av.w};
                float br[4] = {bv.x, bv.y, bv.z, bv.w};
#pragma unroll
                for (int i = 0; i < 4; ++i)
#pragma unroll
                    for (int j = 0; j < 4; ++j) acc[i][j] += ar[i] * br[j];
            }
            if (kt + 1 < NT) {
                const int nb = buf ^ 1;
                As[nb][lk + 0][lr] = pa.x;
                As[nb][lk + 1][lr] = pa.y;
                As[nb][lk + 2][lr] = pa.z;
                As[nb][lk + 3][lr] = pa.w;
                Bs[nb][lk + 0][lr] = pb.x;
                Bs[nb][lk + 1][lr] = pb.y;
                Bs[nb][lk + 2][lr] = pb.z;
                Bs[nb][lk + 3][lr] = pb.w;
                __syncthreads();
            }
        }

        float rs[4], cs[4];
#pragma unroll
        for (int r = 0; r < 4; ++r) rs[r] = g_invn[g_order[ty * 4 + r]];
#pragma unroll
        for (int j = 0; j < 4; ++j) cs[j] = g_invn[cb + tx * 4 + j];
#pragma unroll
        for (int i = 0; i < 4; ++i) {
            float4 v = make_float4(acc[i][0] * rs[i] * cs[0], acc[i][1] * rs[i] * cs[1],
                                   acc[i][2] * rs[i] * cs[2], acc[i][3] * rs[i] * cs[3]);
            *reinterpret_cast<float4*>(C + (size_t)(ty * 4 + i) * 512 + cb + tx * 4) = v;
        }
    }
    gbar(TAILB * 3);

    // ---- P4: reduce f2f partials -> bitmask (blocks 0..63) -------------------
    {
        unsigned char* nib = sraw;
        if (bid < NTOP && tid < 128) {
            float4 s4 = *(reinterpret_cast<const float4*>(g_fp + (size_t)bid * NF) + tid);
#pragma unroll
            for (int sp = 1; sp < KS_F; ++sp) {
                float4 p = *(reinterpret_cast<const float4*>(
                    g_fp + (size_t)sp * NTOP * NF + (size_t)bid * NF) + tid);
                s4.x += p.x; s4.y += p.y; s4.z += p.z; s4.w += p.w;
            }
            nib[tid] = (unsigned char)((s4.x > 0.98f ? 1u : 0u) | (s4.y > 0.98f ? 2u : 0u)
                                     | (s4.z > 0.98f ? 4u : 0u) | (s4.w > 0.98f ? 8u : 0u));
        }
        __syncthreads();
        if (bid < NTOP && tid < 16) {
            unsigned int w = 0;
#pragma unroll
            for (int bq = 0; bq < 8; ++bq) w |= ((unsigned int)nib[8 * tid + bq]) << (4 * bq);
            g_mask[bid * 16 + tid] = w;
        }
    }
    gbar(TAILB * 4);

    // ---- P5: greedy selection scan + output (block 0) ------------------------
    if (bid == 0) {
        unsigned char* vis = sraw;
        unsigned char* sel = sraw + 512;
        unsigned int* msk = reinterpret_cast<unsigned int*>(sraw + 1024);
        vis[tid] = 0; vis[tid + 256] = 0;
        sel[tid] = 0; sel[tid + 256] = 0;
        if (tid == 0) { s_count = 0; s_done = 0; }
        msk[tid] = g_mask[tid];
        msk[tid + 256] = g_mask[tid + 256];
        msk[tid + 512] = g_mask[tid + 512];
        msk[tid + 768] = g_mask[tid + 768];
        __syncthreads();
        for (int pos = 0; pos < NF; ++pos) {
            if (tid == 0) {
                if (s_count >= 32) {
                    s_done = 1;
                } else {
                    int cur = g_order[pos];
                    s_cur = cur;
                    int take = vis[cur] ? 0 : 1;
                    s_take = take;
                    if (take) { sel[cur] = 1; s_count++; }
                }
            }
            __syncthreads();
            if (s_done) break;
            if (s_take) {
#pragma unroll
                for (int h = 0; h < 2; ++h) {
                    const int f = tid + h * 256;
                    bool hit;
                    if (pos < NTOP) {
                        hit = (msk[pos * 16 + (f >> 5)] >> (f & 31)) & 1u;
                    } else {                       // exact fallback (not hit on normal data)
                        const float* a = g_pooled + (size_t)s_cur * EM;
                        const float* bbp = g_pooled + (size_t)f * EM;
                        float d = 0.f;
                        for (int e = 0; e < EM; ++e) d += a[e] * bbp[e];
                        hit = d * g_invn[s_cur] * g_invn[f] > 0.98f;
                    }
                    if (hit) vis[f] = 1;
                }
            }
            __syncthreads();
        }
        __syncthreads();
        out[tid] = (float)sel[tid];
        out[tid + 256] = (float)sel[tid + 256];
        out[NF + tid] = g_gates[tid];
        out[NF + tid + 256] = g_gates[tid + 256];
        __syncthreads();
        if (tid == 0) g_gctr = 0;                  // reset barrier for next replay
    }
}

// ---------------- launch ------------------------------------------------------
extern "C" void kernel_launch(void* const* d_in, const int* in_sizes, int n_in,
                              void* d_out, int out_size) {
    const float* img    = (const float*)d_in[0];
    const float* txt    = (const float*)d_in[1];
    const float* ln_t_g = (const float*)d_in[2];
    const float* ln_t_b = (const float*)d_in[3];
    const float* ln_l_g = (const float*)d_in[4];
    const float* ln_l_b = (const float*)d_in[5];
    const float* W1     = (const float*)d_in[6];
    const float* b1     = (const float*)d_in[7];
    const float* W2     = (const float*)d_in[8];
    const float* b2     = (const float*)d_in[9];
    float* out = (float*)d_out;

    pool_tproj_k<<<NF + 16, POOL_T>>>(img, ln_l_g, ln_l_b,
                                      txt, ln_t_g, ln_t_b, W1, b1);
    gemm_h_k<<<dim3(4, 4, KS_H), 256>>>(W1 + (size_t)EM * HID);
    tail_k<<<TAILB, 256>>>(W2, b2, out);
}